// round 2
// baseline (speedup 1.0000x reference)
#include <cuda_runtime.h>
#include <cuda_bf16.h>
#include <math.h>

// ---------------------------------------------------------------------------
// QBNN attention, fp32 baseline.
// B=2, S=2048, E=1024, H=16, hd=64.
//
// Pipeline:
//  1) gemm_bias:  Q = x@Wq+bq ; K = x@Wk+bk ; V = x@Wv+bv        (4096x1024x1024)
//  2) prep:       Qcat=[Q/8, lam*tanh(Q)@J_h], Kcat=[K, tanh(K)], Vh head-major
//  3) flash:      causal attention, dk=128, dv=64, online softmax
//  4) gemm_bias:  out = O@Wo + bo
// ---------------------------------------------------------------------------

#define N_TOK   4096        // B*S
#define EMB     1024
#define HEADS   16
#define HD      64
#define SEQ     2048
#define BH      32          // B*HEADS

// scratch arena (floats)
#define OFF_Q   0
#define OFF_K   (OFF_Q  + N_TOK*EMB)
#define OFF_V   (OFF_K  + N_TOK*EMB)
#define OFF_QC  (OFF_V  + N_TOK*EMB)          // [BH][SEQ][128]
#define OFF_KC  (OFF_QC + BH*SEQ*128)         // [BH][SEQ][128]
#define OFF_VH  (OFF_KC + BH*SEQ*128)         // [BH][SEQ][64]
#define OFF_O   (OFF_VH + BH*SEQ*64)          // [N_TOK][EMB]
#define SCRATCH_FLOATS (OFF_O + N_TOK*EMB)

__device__ float g_scratch[SCRATCH_FLOATS];

// ---------------------------------------------------------------------------
// GEMM: C[M x 1024] = A[M x 1024] @ W[1024 x 1024] + bias
// 128x128 block tile, 8-deep K tiles, 256 threads, 8x8 micro-tile.
// ---------------------------------------------------------------------------
__global__ __launch_bounds__(256, 2)
void gemm_bias_kernel(const float* __restrict__ A, const float* __restrict__ W,
                      const float* __restrict__ bias, float* __restrict__ C, int M)
{
    const int K = 1024, N = 1024;
    __shared__ float Ast[8 * 132];   // [k][m], stride 132
    __shared__ float Bs [8 * 132];   // [k][n], stride 132

    int tid = threadIdx.x;
    int tx  = tid & 15;              // 0..15 (cols)
    int ty  = tid >> 4;              // 0..15 (rows)
    int m0  = blockIdx.y * 128;
    int n0  = blockIdx.x * 128;

    int arow  = tid >> 1;            // 0..127
    int acol4 = (tid & 1) * 4;       // 0 or 4
    int brow  = tid >> 5;            // 0..7
    int bcol4 = (tid & 31) * 4;      // 0..124

    float acc[8][8];
#pragma unroll
    for (int i = 0; i < 8; i++)
#pragma unroll
        for (int j = 0; j < 8; j++) acc[i][j] = 0.f;

    for (int k0 = 0; k0 < K; k0 += 8) {
        float4 av = *(const float4*)&A[(size_t)(m0 + arow) * K + k0 + acol4];
        float4 bv = *(const float4*)&W[(size_t)(k0 + brow) * N + n0 + bcol4];
        __syncthreads();
        Ast[(acol4 + 0) * 132 + arow] = av.x;
        Ast[(acol4 + 1) * 132 + arow] = av.y;
        Ast[(acol4 + 2) * 132 + arow] = av.z;
        Ast[(acol4 + 3) * 132 + arow] = av.w;
        *(float4*)&Bs[brow * 132 + bcol4] = bv;
        __syncthreads();
#pragma unroll
        for (int k = 0; k < 8; k++) {
            float a[8], b[8];
            *(float4*)&a[0] = *(const float4*)&Ast[k * 132 + ty * 8];
            *(float4*)&a[4] = *(const float4*)&Ast[k * 132 + ty * 8 + 4];
            *(float4*)&b[0] = *(const float4*)&Bs [k * 132 + tx * 8];
            *(float4*)&b[4] = *(const float4*)&Bs [k * 132 + tx * 8 + 4];
#pragma unroll
            for (int i = 0; i < 8; i++)
#pragma unroll
                for (int j = 0; j < 8; j++)
                    acc[i][j] += a[i] * b[j];
        }
    }

    float bb[8];
    *(float4*)&bb[0] = *(const float4*)&bias[n0 + tx * 8];
    *(float4*)&bb[4] = *(const float4*)&bias[n0 + tx * 8 + 4];

#pragma unroll
    for (int i = 0; i < 8; i++) {
        size_t row = (size_t)(m0 + ty * 8 + i);
        float4 w0 = make_float4(acc[i][0] + bb[0], acc[i][1] + bb[1],
                                acc[i][2] + bb[2], acc[i][3] + bb[3]);
        float4 w1 = make_float4(acc[i][4] + bb[4], acc[i][5] + bb[5],
                                acc[i][6] + bb[6], acc[i][7] + bb[7]);
        *(float4*)&C[row * N + n0 + tx * 8]     = w0;
        *(float4*)&C[row * N + n0 + tx * 8 + 4] = w1;
    }
}

// ---------------------------------------------------------------------------
// prep: build Qcat, Kcat, Vh (head-major). Block: (64 dims x 8 tokens), one head.
// ---------------------------------------------------------------------------
__global__ __launch_bounds__(512)
void prep_kernel(const float* __restrict__ Qb, const float* __restrict__ Kb,
                 const float* __restrict__ Vb, const float* __restrict__ J,
                 const float* __restrict__ lamp,
                 float* __restrict__ Qcat, float* __restrict__ Kcat,
                 float* __restrict__ Vh)
{
    __shared__ float Js[4096];       // J[h] 64x64
    __shared__ float qn[8][64];

    int h   = blockIdx.y;
    int d   = threadIdx.x;           // 0..63
    int ty  = threadIdx.y;           // 0..7
    int tid = ty * 64 + d;

    for (int i = tid; i < 4096; i += 512) Js[i] = J[h * 4096 + i];

    int tok = blockIdx.x * 8 + ty;
    int b   = tok >> 11;
    int s   = tok & 2047;
    int bh  = (b << 4) + h;

    float q = Qb[(size_t)tok * EMB + h * HD + d];
    float k = Kb[(size_t)tok * EMB + h * HD + d];
    float v = Vb[(size_t)tok * EMB + h * HD + d];
    qn[ty][d] = tanhf(q);
    __syncthreads();

    float accv = 0.f;
#pragma unroll 8
    for (int dd = 0; dd < 64; dd++) accv += qn[ty][dd] * Js[dd * 64 + d];

    float lam = lamp[0];
    size_t base = (size_t)bh * SEQ + s;
    Qcat[base * 128 + d]      = q * 0.125f;      // 1/sqrt(64)
    Qcat[base * 128 + 64 + d] = lam * accv;
    Kcat[base * 128 + d]      = k;
    Kcat[base * 128 + 64 + d] = tanhf(k);
    Vh  [base * 64  + d]      = v;
}

// ---------------------------------------------------------------------------
// flash: causal attention, dk=128, dv=64. Tile 64q x 64k, 256 threads,
// 4x4 micro-tile per thread (16x16 thread grid).
// smem: Qst[128][68] (transposed), Kst[128][68] (transposed), Vs[64][64], Pst[64][68].
// ---------------------------------------------------------------------------
#define FL_SMEM_FLOATS (128*68 + 128*68 + 64*64 + 64*68)
#define FL_SMEM_BYTES  (FL_SMEM_FLOATS * 4)

__global__ __launch_bounds__(256, 1)
void flash_kernel(const float* __restrict__ Qcat, const float* __restrict__ Kcat,
                  const float* __restrict__ Vh, float* __restrict__ O)
{
    extern __shared__ float sm[];
    float* Qst = sm;                       // [d][r] stride 68
    float* Kst = Qst + 128 * 68;           // [d][j] stride 68
    float* Vs  = Kst + 128 * 68;           // [j][c] stride 64
    float* Pst = Vs  + 64 * 64;            // [j][r] stride 68

    int bh  = blockIdx.y;
    int qt  = gridDim.x - 1 - blockIdx.x;  // heavy tiles scheduled first
    int tid = threadIdx.x;
    int tr  = tid >> 4;                    // 0..15 -> rows tr*4..+3
    int tc  = tid & 15;                    // 0..15 -> cols tc*4..+3

    const float* Qg = Qcat + ((size_t)bh * SEQ + qt * 64) * 128;
    for (int idx = tid; idx < 2048; idx += 256) {      // 64 rows * 32 float4
        int r  = idx >> 5;
        int d4 = (idx & 31) << 2;
        float4 v = *(const float4*)&Qg[r * 128 + d4];
        Qst[(d4 + 0) * 68 + r] = v.x;
        Qst[(d4 + 1) * 68 + r] = v.y;
        Qst[(d4 + 2) * 68 + r] = v.z;
        Qst[(d4 + 3) * 68 + r] = v.w;
    }

    float acc[4][4];
#pragma unroll
    for (int i = 0; i < 4; i++)
#pragma unroll
        for (int j = 0; j < 4; j++) acc[i][j] = 0.f;
    float mrow[4] = {-1e30f, -1e30f, -1e30f, -1e30f};
    float lrow[4] = {0.f, 0.f, 0.f, 0.f};

    for (int kt = 0; kt <= qt; kt++) {
        __syncthreads();   // protect Kst/Vs/Pst from previous iteration readers
        const float* Kg = Kcat + ((size_t)bh * SEQ + kt * 64) * 128;
        const float* Vg = Vh   + ((size_t)bh * SEQ + kt * 64) * 64;
        for (int idx = tid; idx < 2048; idx += 256) {
            int r  = idx >> 5;
            int d4 = (idx & 31) << 2;
            float4 v = *(const float4*)&Kg[r * 128 + d4];
            Kst[(d4 + 0) * 68 + r] = v.x;
            Kst[(d4 + 1) * 68 + r] = v.y;
            Kst[(d4 + 2) * 68 + r] = v.z;
            Kst[(d4 + 3) * 68 + r] = v.w;
        }
        for (int idx = tid; idx < 1024; idx += 256) {  // 64 rows * 16 float4
            int j  = idx >> 4;
            int c4 = (idx & 15) << 2;
            *(float4*)&Vs[j * 64 + c4] = *(const float4*)&Vg[j * 64 + c4];
        }
        __syncthreads();

        float s[4][4];
#pragma unroll
        for (int i = 0; i < 4; i++)
#pragma unroll
            for (int j = 0; j < 4; j++) s[i][j] = 0.f;

#pragma unroll 4
        for (int d = 0; d < 128; d++) {
            float4 qv = *(const float4*)&Qst[d * 68 + tr * 4];
            float4 kv = *(const float4*)&Kst[d * 68 + tc * 4];
            float q0 = qv.x, q1 = qv.y, q2 = qv.z, q3 = qv.w;
            float k0 = kv.x, k1 = kv.y, k2 = kv.z, k3 = kv.w;
            s[0][0] += q0 * k0; s[0][1] += q0 * k1; s[0][2] += q0 * k2; s[0][3] += q0 * k3;
            s[1][0] += q1 * k0; s[1][1] += q1 * k1; s[1][2] += q1 * k2; s[1][3] += q1 * k3;
            s[2][0] += q2 * k0; s[2][1] += q2 * k1; s[2][2] += q2 * k2; s[2][3] += q2 * k3;
            s[3][0] += q3 * k0; s[3][1] += q3 * k1; s[3][2] += q3 * k2; s[3][3] += q3 * k3;
        }

        if (kt == qt) {   // diagonal tile: apply causal mask
#pragma unroll
            for (int ri = 0; ri < 4; ri++) {
                int ig = tr * 4 + ri;
#pragma unroll
                for (int jc = 0; jc < 4; jc++) {
                    if (tc * 4 + jc > ig) s[ri][jc] = -1e30f;
                }
            }
        }

        // online softmax update (row group = 16 lanes sharing tr)
#pragma unroll
        for (int ri = 0; ri < 4; ri++) {
            float tm = fmaxf(fmaxf(s[ri][0], s[ri][1]), fmaxf(s[ri][2], s[ri][3]));
            tm = fmaxf(tm, __shfl_xor_sync(0xffffffffu, tm, 1));
            tm = fmaxf(tm, __shfl_xor_sync(0xffffffffu, tm, 2));
            tm = fmaxf(tm, __shfl_xor_sync(0xffffffffu, tm, 4));
            tm = fmaxf(tm, __shfl_xor_sync(0xffffffffu, tm, 8));
            float mnew = fmaxf(mrow[ri], tm);
            float corr = __expf(mrow[ri] - mnew);
            mrow[ri] = mnew;
            float ps = 0.f;
#pragma unroll
            for (int jc = 0; jc < 4; jc++) {
                float p = __expf(s[ri][jc] - mnew);
                s[ri][jc] = p;
                ps += p;
            }
            ps += __shfl_xor_sync(0xffffffffu, ps, 1);
            ps += __shfl_xor_sync(0xffffffffu, ps, 2);
            ps += __shfl_xor_sync(0xffffffffu, ps, 4);
            ps += __shfl_xor_sync(0xffffffffu, ps, 8);
            lrow[ri] = lrow[ri] * corr + ps;
#pragma unroll
            for (int cc = 0; cc < 4; cc++) acc[ri][cc] *= corr;
        }

        // write P transposed: Pst[j][r]
#pragma unroll
        for (int jc = 0; jc < 4; jc++) {
            float4 w = make_float4(s[0][jc], s[1][jc], s[2][jc], s[3][jc]);
            *(float4*)&Pst[(tc * 4 + jc) * 68 + tr * 4] = w;
        }
        __syncthreads();

        // O += P @ V
#pragma unroll 4
        for (int j = 0; j < 64; j++) {
            float4 pv = *(const float4*)&Pst[j * 68 + tr * 4];
            float4 vv = *(const float4*)&Vs [j * 64 + tc * 4];
            float p0 = pv.x, p1 = pv.y, p2 = pv.z, p3 = pv.w;
            float v0 = vv.x, v1 = vv.y, v2 = vv.z, v3 = vv.w;
            acc[0][0] += p0 * v0; acc[0][1] += p0 * v1; acc[0][2] += p0 * v2; acc[0][3] += p0 * v3;
            acc[1][0] += p1 * v0; acc[1][1] += p1 * v1; acc[1][2] += p1 * v2; acc[1][3] += p1 * v3;
            acc[2][0] += p2 * v0; acc[2][1] += p2 * v1; acc[2][2] += p2 * v2; acc[2][3] += p2 * v3;
            acc[3][0] += p3 * v0; acc[3][1] += p3 * v1; acc[3][2] += p3 * v2; acc[3][3] += p3 * v3;
        }
    }

    // epilogue: normalize + write to token-major O (B,S,E)
    int b = bh >> 4;
    int h = bh & 15;
    float* Og = O + ((size_t)(b * SEQ + qt * 64)) * EMB + h * HD;
#pragma unroll
    for (int ri = 0; ri < 4; ri++) {
        float inv = 1.0f / lrow[ri];
        float4 o = make_float4(acc[ri][0] * inv, acc[ri][1] * inv,
                               acc[ri][2] * inv, acc[ri][3] * inv);
        *(float4*)&Og[(size_t)(tr * 4 + ri) * EMB + tc * 4] = o;
    }
}

// ---------------------------------------------------------------------------
// launch
// ---------------------------------------------------------------------------
extern "C" void kernel_launch(void* const* d_in, const int* in_sizes, int n_in,
                              void* d_out, int out_size)
{
    const float* x   = (const float*)d_in[0];
    const float* Wq  = (const float*)d_in[1];
    const float* bq  = (const float*)d_in[2];
    const float* Wk  = (const float*)d_in[3];
    const float* bk  = (const float*)d_in[4];
    const float* Wv  = (const float*)d_in[5];
    const float* bv  = (const float*)d_in[6];
    const float* Wo  = (const float*)d_in[7];
    const float* bo  = (const float*)d_in[8];
    const float* J   = (const float*)d_in[9];
    const float* lam = (const float*)d_in[10];
    float* out = (float*)d_out;

    void* scratch_v = nullptr;
    cudaGetSymbolAddress(&scratch_v, g_scratch);
    float* scr  = (float*)scratch_v;
    float* gQ   = scr + OFF_Q;
    float* gK   = scr + OFF_K;
    float* gV   = scr + OFF_V;
    float* gQC  = scr + OFF_QC;
    float* gKC  = scr + OFF_KC;
    float* gVH  = scr + OFF_VH;
    float* gO   = scr + OFF_O;

    dim3 gemm_grid(8, N_TOK / 128);
    dim3 gemm_blk(256);

    gemm_bias_kernel<<<gemm_grid, gemm_blk>>>(x, Wq, bq, gQ, N_TOK);
    gemm_bias_kernel<<<gemm_grid, gemm_blk>>>(x, Wk, bk, gK, N_TOK);
    gemm_bias_kernel<<<gemm_grid, gemm_blk>>>(x, Wv, bv, gV, N_TOK);

    dim3 prep_grid(N_TOK / 8, HEADS);
    dim3 prep_blk(64, 8);
    prep_kernel<<<prep_grid, prep_blk>>>(gQ, gK, gV, J, lam, gQC, gKC, gVH);

    cudaFuncSetAttribute(flash_kernel, cudaFuncAttributeMaxDynamicSharedMemorySize,
                         FL_SMEM_BYTES);
    dim3 fl_grid(SEQ / 64, BH);
    flash_kernel<<<fl_grid, 256, FL_SMEM_BYTES>>>(gQC, gKC, gVH, gO);

    gemm_bias_kernel<<<gemm_grid, gemm_blk>>>(gO, Wo, bo, out, N_TOK);
}